// round 15
// baseline (speedup 1.0000x reference)
#include <cuda_runtime.h>
#include <cstdint>

#define BB     16
#define NIN    1024
#define MM     512
#define NCHUNK 18                 // 16 chunks of 57 + 2 of 56 = 1024
#define CH_BIG 57
#define BPG    2                  // batches per CTA (register budget bound)
#define LOG2E  1.4426950408889634f
#define LN_EPS 1e-5f

typedef unsigned long long u64;

// Deterministic per-chunk partial accumulators for nv: [chunk][b][m][16]
__device__ float g_partial[NCHUNK * BB * MM * 16];

__device__ __forceinline__ u64 pack2(float lo, float hi) {
    u64 r; asm("mov.b64 %0,{%1,%2};" : "=l"(r) : "f"(lo), "f"(hi)); return r;
}
__device__ __forceinline__ void unpack2(u64 v, float& lo, float& hi) {
    asm("mov.b64 {%0,%1},%2;" : "=f"(lo), "=f"(hi) : "l"(v));
}
__device__ __forceinline__ u64 fma2(u64 a, u64 b, u64 c) {
    u64 d; asm("fma.rn.f32x2 %0,%1,%2,%3;" : "=l"(d) : "l"(a), "l"(b), "l"(c)); return d;
}
__device__ __forceinline__ u64 add2(u64 a, u64 b) {
    u64 d; asm("add.rn.f32x2 %0,%1,%2;" : "=l"(d) : "l"(a), "l"(b)); return d;
}
__device__ __forceinline__ u64 mul2(u64 a, u64 b) {
    u64 d; asm("mul.rn.f32x2 %0,%1,%2;" : "=l"(d) : "l"(a), "l"(b)); return d;
}
__device__ __forceinline__ float ex2f(float x) {
    float y; asm("ex2.approx.f32 %0,%1;" : "=f"(y) : "f"(x)); return y;
}
__device__ __forceinline__ float rcpf(float x) {
    float y; asm("rcp.approx.f32 %0,%1;" : "=f"(y) : "f"(x)); return y;
}
__device__ __forceinline__ void stcs(float* p, float v) {
    asm volatile("st.global.cs.f32 [%0],%1;" :: "l"(p), "f"(v) : "memory");
}
// Packed fp16 exp2: one MUFU ex2 for both halves of an f32x2 (round-13 win).
__device__ __forceinline__ u64 ex2_f16x2_pair(u64 t) {
    float lo, hi;
    unpack2(t, lo, hi);
    unsigned int h, eh;
    asm("cvt.rn.f16x2.f32 %0,%1,%2;" : "=r"(h) : "f"(hi), "f"(lo)); // hi->msb, lo->lsb
    asm("ex2.approx.f16x2 %0,%1;" : "=r"(eh) : "r"(h));
    float elo, ehi;
    asm("{\n\t.reg .b16 l,u;\n\tmov.b32 {l,u},%2;\n\t"
        "cvt.f32.f16 %0,l;\n\tcvt.f32.f16 %1,u;\n\t}"
        : "=f"(elo), "=f"(ehi) : "r"(eh));
    return pack2(elo, ehi);
}

// Chunk partitioning: chunks 0..15 have 57 rows, chunks 16..17 have 56.
__device__ __host__ __forceinline__ int chunk_start(int c) {
    return (c < 16) ? (CH_BIG * c) : (912 + 56 * (c - 16));
}
__device__ __host__ __forceinline__ int chunk_len(int c) {
    return (c < 16) ? CH_BIG : 56;
}

// Round-14 winner with ONE change: the post-barrier block-sum chain
// (LDS -> 4xSHFL -> 2x bcast, ~185 cyc phase-locked across all warps) is
// replaced by 8 independent broadcast LDS.128 + a short FADD tree (~60 cyc;
// all loads pipeline behind one 29-cyc latency). Round 11 tested this change
// confounded with a bad pose-loop edit; this isolates it.
__global__ __launch_bounds__(512, 1)
void caps_main(const float* __restrict__ x,     // [B, NIN, 16]
               const float* __restrict__ w,     // [NIN, 4, 4, MM]
               const float* __restrict__ V,     // [MM, 16]
               float* __restrict__ agree_out)   // [B, NIN, MM]
{
    __shared__ u64  xsd[BPG][CH_BIG][16];        // dup-packed, LOG2E-prescaled x
    __shared__ __align__(16) float sred[2][32];  // [buf][bb*16 + wid]

    const int tid   = threadIdx.x;          // m
    const int wid   = tid >> 5;
    const int lane  = tid & 31;
    const int chunk = blockIdx.x % NCHUNK;
    const int bp    = blockIdx.x / NCHUNK;  // 0..7
    const int b0    = bp * BPG;
    const int n0    = chunk_start(chunk);
    const int len   = chunk_len(chunk);

    // Stage + rescale + duplicate x into shared.
    for (int idx = tid; idx < BPG * len * 16; idx += 512) {
        const int bb  = idx / (len * 16);
        const int rem = idx % (len * 16);
        const int i   = rem >> 4;
        const int j   = rem & 15;
        const float v = x[(((size_t)(b0 + bb) * NIN) + n0 + i) * 16 + j] * LOG2E;
        xsd[bb][i][j] = pack2(v, v);
    }

    // Packed initial query: Vq2[a*2+dp] = {V[m][a*4+2dp], V[m][a*4+2dp+1]}.
    u64 Vq2[8];
    {
        const float* vm = V + (size_t)tid * 16;
#pragma unroll
        for (int k = 0; k < 8; k++) Vq2[k] = pack2(vm[2 * k], vm[2 * k + 1]);
    }

    u64 acc2[BPG][8];
#pragma unroll
    for (int bb = 0; bb < BPG; bb++)
#pragma unroll
        for (int k = 0; k < 8; k++) acc2[bb][k] = 0ull;

    __syncthreads();

    const float* wbase = w + (size_t)n0 * (16 * MM) + tid;

    // Prefetch w for iteration 0.
    float wn[16];
#pragma unroll
    for (int s = 0; s < 16; s++) wn[s] = wbase[(size_t)s * MM];

    for (int i = 0; i < len; i++) {
        // Pack current w into d-pairs: wpair[x*2+dp] = {w[x*4+2dp], w[x*4+2dp+1]}.
        u64 wpair[8];
#pragma unroll
        for (int k = 0; k < 8; k++) wpair[k] = pack2(wn[2 * k], wn[2 * k + 1]);

        // Prefetch next iteration's w (hidden behind this iteration's math).
        if (i + 1 < len) {
            const float* wp = wbase + (size_t)(i + 1) * 16 * MM;
#pragma unroll
            for (int s = 0; s < 16; s++) wn[s] = wp[(size_t)s * MM];
        }

        u64 e2[BPG][8];
        float inv[BPG], eag[BPG];

#pragma unroll
        for (int bb = 0; bb < BPG; bb++) {
            // Pose transform: 32 packed FMA.
            u64 t2[8];
#pragma unroll
            for (int a = 0; a < 4; a++) {
#pragma unroll
                for (int dp = 0; dp < 2; dp++) {
                    u64 acc = mul2(xsd[bb][i][a * 4 + 0], wpair[0 * 2 + dp]);
                    acc = fma2(xsd[bb][i][a * 4 + 1], wpair[1 * 2 + dp], acc);
                    acc = fma2(xsd[bb][i][a * 4 + 2], wpair[2 * 2 + dp], acc);
                    acc = fma2(xsd[bb][i][a * 4 + 3], wpair[3 * 2 + dp], acc);
                    t2[a * 2 + dp] = acc;
                }
            }
            // exp (log2-domain) via packed fp16 MUFU: one ex2 per f32x2 pair.
#pragma unroll
            for (int k = 0; k < 8; k++)
                e2[bb][k] = ex2_f16x2_pair(t2[k]);
            // Inner-softmax denominator.
            u64 s01 = add2(add2(e2[bb][0], e2[bb][1]), add2(e2[bb][2], e2[bb][3]));
            u64 s23 = add2(add2(e2[bb][4], e2[bb][5]), add2(e2[bb][6], e2[bb][7]));
            u64 st  = add2(s01, s23);
            float slo, shi; unpack2(st, slo, shi);
            inv[bb] = rcpf(slo + shi);
            // Agreement dot with Vq (f32).
            u64 g = mul2(e2[bb][0], Vq2[0]);
#pragma unroll
            for (int k = 1; k < 8; k++) g = fma2(e2[bb][k], Vq2[k], g);
            float glo, ghi; unpack2(g, glo, ghi);
            const float ag = (glo + ghi) * inv[bb];
            stcs(agree_out + (((size_t)(b0 + bb) * NIN) + n0 + i) * MM + tid, ag);
            eag[bb] = ex2f(ag * LOG2E);   // |ag| <= 1, max-free softmax safe (f32)
        }

        // Pre-barrier: per-warp partials of exp(ag) for both b's.
        float v0 = eag[0], v1 = eag[1];
#pragma unroll
        for (int o = 16; o > 0; o >>= 1) {
            v0 += __shfl_xor_sync(0xffffffffu, v0, o);
            v1 += __shfl_xor_sync(0xffffffffu, v1, o);
        }
        const int buf = i & 1;
        if (lane == 0) { sred[buf][wid] = v0; sred[buf][16 + wid] = v1; }
        __syncthreads();

        // Post-barrier: sum the 32 warp partials via 8 independent broadcast
        // LDS.128 + FADD tree (short chain, bit-identical across threads).
        const float4* sp = (const float4*)&sred[buf][0];
        const float4 p0 = sp[0], p1 = sp[1], p2 = sp[2], p3 = sp[3];
        const float4 p4 = sp[4], p5 = sp[5], p6 = sp[6], p7 = sp[7];
        const float S0 = (((p0.x + p0.y) + (p0.z + p0.w)) +
                          ((p1.x + p1.y) + (p1.z + p1.w))) +
                         (((p2.x + p2.y) + (p2.z + p2.w)) +
                          ((p3.x + p3.y) + (p3.z + p3.w)));
        const float S1 = (((p4.x + p4.y) + (p4.z + p4.w)) +
                          ((p5.x + p5.y) + (p5.z + p5.w))) +
                         (((p6.x + p6.y) + (p6.z + p6.w)) +
                          ((p7.x + p7.y) + (p7.z + p7.w)));

        const float q0 = eag[0] * rcpf(S0) * inv[0];
        const float q1 = eag[1] * rcpf(S1) * inv[1];
        const u64 q0d = pack2(q0, q0);
        const u64 q1d = pack2(q1, q1);
#pragma unroll
        for (int k = 0; k < 8; k++) {
            acc2[0][k] = fma2(q0d, e2[0][k], acc2[0][k]);
            acc2[1][k] = fma2(q1d, e2[1][k], acc2[1][k]);
        }
    }

    // acc2[bb] as u64[8] is already float[16] in natural slot order.
#pragma unroll
    for (int bb = 0; bb < BPG; bb++) {
        float4* dst = (float4*)(g_partial +
            ((((size_t)chunk * BB + (b0 + bb)) * MM + tid) << 4));
#pragma unroll
        for (int q = 0; q < 4; q++) {
            float xx, yy, zz, ww;
            unpack2(acc2[bb][2 * q],     xx, yy);
            unpack2(acc2[bb][2 * q + 1], zz, ww);
            dst[q] = make_float4(xx, yy, zz, ww);
        }
    }
}

// Reduce chunk partials + LayerNorm. 8 lanes cooperate per (b,m) row:
// q = float4 quarter (0..3), h = chunk half (0..1; 9 chunks each).
__global__ __launch_bounds__(256)
void caps_ln(const float* __restrict__ gamma,
             const float* __restrict__ beta,
             float* __restrict__ nv_out)  // [B*MM, 16]
{
    const int t   = blockIdx.x * 256 + threadIdx.x;  // 0 .. B*MM*8-1
    const int row = t >> 3;
    const int q   = t & 3;
    const int h   = (t >> 2) & 1;
    const int b   = row / MM;
    const int m   = row % MM;

    float4 v = make_float4(0.f, 0.f, 0.f, 0.f);
#pragma unroll
    for (int cc = 0; cc < NCHUNK / 2; cc++) {
        const int c = h * (NCHUNK / 2) + cc;
        const float4 p = *(const float4*)(g_partial +
            ((((size_t)c * BB + b) * MM + m) << 4) + q * 4);
        v.x += p.x; v.y += p.y; v.z += p.z; v.w += p.w;
    }
    // Combine chunk halves (lanes differ in bit 2).
    v.x += __shfl_xor_sync(0xffffffffu, v.x, 4);
    v.y += __shfl_xor_sync(0xffffffffu, v.y, 4);
    v.z += __shfl_xor_sync(0xffffffffu, v.z, 4);
    v.w += __shfl_xor_sync(0xffffffffu, v.w, 4);

    // Row stats across the 4 q-lanes (bits 0-1).
    float s = v.x + v.y + v.z + v.w;
    s += __shfl_xor_sync(0xffffffffu, s, 1);
    s += __shfl_xor_sync(0xffffffffu, s, 2);
    const float mu = s * (1.0f / 16.0f);

    const float d0 = v.x - mu, d1 = v.y - mu, d2 = v.z - mu, d3 = v.w - mu;
    float ss = d0 * d0 + d1 * d1 + d2 * d2 + d3 * d3;
    ss += __shfl_xor_sync(0xffffffffu, ss, 1);
    ss += __shfl_xor_sync(0xffffffffu, ss, 2);
    const float rs = rsqrtf(ss * (1.0f / 16.0f) + LN_EPS);

    if (h == 0) {
        const float4 gm = *(const float4*)(gamma + q * 4);
        const float4 bt = *(const float4*)(beta + q * 4);
        float4 o;
        o.x = d0 * rs * gm.x + bt.x;
        o.y = d1 * rs * gm.y + bt.y;
        o.z = d2 * rs * gm.z + bt.z;
        o.w = d3 * rs * gm.w + bt.w;
        *(float4*)(nv_out + (size_t)row * 16 + q * 4) = o;
    }
}

extern "C" void kernel_launch(void* const* d_in, const int* in_sizes, int n_in,
                              void* d_out, int out_size)
{
    // metadata order: input, num_iter, w, V, gamma, beta
    const float* x     = (const float*)d_in[0];
    const float* w     = (const float*)d_in[2];
    const float* V     = (const float*)d_in[3];
    const float* gamma = (const float*)d_in[4];
    const float* beta  = (const float*)d_in[5];

    float* out    = (float*)d_out;
    float* nv_out = out;                          // [16,512,16]   = 131072
    float* agree  = out + (size_t)BB * MM * 16;   // [16,1024,512] = 8388608

    caps_main<<<NCHUNK * (BB / BPG), 512>>>(x, w, V, agree);
    caps_ln<<<(BB * MM * 8) / 256, 256>>>(gamma, beta, nv_out);
}

// round 16
// speedup vs baseline: 1.1015x; 1.1015x over previous
#include <cuda_runtime.h>
#include <cstdint>

#define BB     16
#define NIN    1024
#define MM     512
#define NCHUNK 18                 // 16 chunks of 57 + 2 of 56 = 1024
#define CH_BIG 57
#define BPG    2                  // batches per CTA (register budget bound)
#define LOG2E  1.4426950408889634f
#define LN_EPS 1e-5f

typedef unsigned long long u64;

// Deterministic per-chunk partial accumulators for nv: [chunk][b][m][16]
__device__ float g_partial[NCHUNK * BB * MM * 16];

__device__ __forceinline__ u64 pack2(float lo, float hi) {
    u64 r; asm("mov.b64 %0,{%1,%2};" : "=l"(r) : "f"(lo), "f"(hi)); return r;
}
__device__ __forceinline__ void unpack2(u64 v, float& lo, float& hi) {
    asm("mov.b64 {%0,%1},%2;" : "=f"(lo), "=f"(hi) : "l"(v));
}
__device__ __forceinline__ u64 fma2(u64 a, u64 b, u64 c) {
    u64 d; asm("fma.rn.f32x2 %0,%1,%2,%3;" : "=l"(d) : "l"(a), "l"(b), "l"(c)); return d;
}
__device__ __forceinline__ u64 add2(u64 a, u64 b) {
    u64 d; asm("add.rn.f32x2 %0,%1,%2;" : "=l"(d) : "l"(a), "l"(b)); return d;
}
__device__ __forceinline__ u64 mul2(u64 a, u64 b) {
    u64 d; asm("mul.rn.f32x2 %0,%1,%2;" : "=l"(d) : "l"(a), "l"(b)); return d;
}
__device__ __forceinline__ float ex2f(float x) {
    float y; asm("ex2.approx.f32 %0,%1;" : "=f"(y) : "f"(x)); return y;
}
__device__ __forceinline__ float rcpf(float x) {
    float y; asm("rcp.approx.f32 %0,%1;" : "=f"(y) : "f"(x)); return y;
}
__device__ __forceinline__ void stcs(float* p, float v) {
    asm volatile("st.global.cs.f32 [%0],%1;" :: "l"(p), "f"(v) : "memory");
}
// Packed fp16 exp2: one MUFU ex2 for both halves of an f32x2 (round-13 win).
__device__ __forceinline__ u64 ex2_f16x2_pair(u64 t) {
    float lo, hi;
    unpack2(t, lo, hi);
    unsigned int h, eh;
    asm("cvt.rn.f16x2.f32 %0,%1,%2;" : "=r"(h) : "f"(hi), "f"(lo)); // hi->msb, lo->lsb
    asm("ex2.approx.f16x2 %0,%1;" : "=r"(eh) : "r"(h));
    float elo, ehi;
    asm("{\n\t.reg .b16 l,u;\n\tmov.b32 {l,u},%2;\n\t"
        "cvt.f32.f16 %0,l;\n\tcvt.f32.f16 %1,u;\n\t}"
        : "=f"(elo), "=f"(ehi) : "r"(eh));
    return pack2(elo, ehi);
}

// Chunk partitioning: chunks 0..15 have 57 rows, chunks 16..17 have 56.
__device__ __host__ __forceinline__ int chunk_start(int c) {
    return (c < 16) ? (CH_BIG * c) : (912 + 56 * (c - 16));
}
__device__ __host__ __forceinline__ int chunk_len(int c) {
    return (c < 16) ? CH_BIG : 56;
}

// Round-14 winner (84.4us) with ONE change: the pre-barrier per-warp sums of
// exp(ag) use a half-warp split — one cross-half swap (lanes exchange bb
// roles via shfl.xor 16) then 4 xor levels inside each half — 5 SHFL total
// instead of 10 and one level shallower into the barrier. Lanes 0-15 end
// with the warp's bb0 partial, lanes 16-31 with bb1; lane 0/16 store.
__global__ __launch_bounds__(512, 1)
void caps_main(const float* __restrict__ x,     // [B, NIN, 16]
               const float* __restrict__ w,     // [NIN, 4, 4, MM]
               const float* __restrict__ V,     // [MM, 16]
               float* __restrict__ agree_out)   // [B, NIN, MM]
{
    __shared__ u64  xsd[BPG][CH_BIG][16];  // dup-packed, LOG2E-prescaled x
    __shared__ float sred[2][32];          // [buf][bb*16 + wid]

    const int tid   = threadIdx.x;          // m
    const int wid   = tid >> 5;
    const int lane  = tid & 31;
    const int chunk = blockIdx.x % NCHUNK;
    const int bp    = blockIdx.x / NCHUNK;  // 0..7
    const int b0    = bp * BPG;
    const int n0    = chunk_start(chunk);
    const int len   = chunk_len(chunk);

    // Stage + rescale + duplicate x into shared.
    for (int idx = tid; idx < BPG * len * 16; idx += 512) {
        const int bb  = idx / (len * 16);
        const int rem = idx % (len * 16);
        const int i   = rem >> 4;
        const int j   = rem & 15;
        const float v = x[(((size_t)(b0 + bb) * NIN) + n0 + i) * 16 + j] * LOG2E;
        xsd[bb][i][j] = pack2(v, v);
    }

    // Packed initial query: Vq2[a*2+dp] = {V[m][a*4+2dp], V[m][a*4+2dp+1]}.
    u64 Vq2[8];
    {
        const float* vm = V + (size_t)tid * 16;
#pragma unroll
        for (int k = 0; k < 8; k++) Vq2[k] = pack2(vm[2 * k], vm[2 * k + 1]);
    }

    u64 acc2[BPG][8];
#pragma unroll
    for (int bb = 0; bb < BPG; bb++)
#pragma unroll
        for (int k = 0; k < 8; k++) acc2[bb][k] = 0ull;

    __syncthreads();

    const float* wbase = w + (size_t)n0 * (16 * MM) + tid;

    // Prefetch w for iteration 0.
    float wn[16];
#pragma unroll
    for (int s = 0; s < 16; s++) wn[s] = wbase[(size_t)s * MM];

    for (int i = 0; i < len; i++) {
        // Pack current w into d-pairs: wpair[x*2+dp] = {w[x*4+2dp], w[x*4+2dp+1]}.
        u64 wpair[8];
#pragma unroll
        for (int k = 0; k < 8; k++) wpair[k] = pack2(wn[2 * k], wn[2 * k + 1]);

        // Prefetch next iteration's w (hidden behind this iteration's math).
        if (i + 1 < len) {
            const float* wp = wbase + (size_t)(i + 1) * 16 * MM;
#pragma unroll
            for (int s = 0; s < 16; s++) wn[s] = wp[(size_t)s * MM];
        }

        u64 e2[BPG][8];
        float inv[BPG], eag[BPG];

#pragma unroll
        for (int bb = 0; bb < BPG; bb++) {
            // Pose transform: 32 packed FMA.
            u64 t2[8];
#pragma unroll
            for (int a = 0; a < 4; a++) {
#pragma unroll
                for (int dp = 0; dp < 2; dp++) {
                    u64 acc = mul2(xsd[bb][i][a * 4 + 0], wpair[0 * 2 + dp]);
                    acc = fma2(xsd[bb][i][a * 4 + 1], wpair[1 * 2 + dp], acc);
                    acc = fma2(xsd[bb][i][a * 4 + 2], wpair[2 * 2 + dp], acc);
                    acc = fma2(xsd[bb][i][a * 4 + 3], wpair[3 * 2 + dp], acc);
                    t2[a * 2 + dp] = acc;
                }
            }
            // exp (log2-domain) via packed fp16 MUFU: one ex2 per f32x2 pair.
#pragma unroll
            for (int k = 0; k < 8; k++)
                e2[bb][k] = ex2_f16x2_pair(t2[k]);
            // Inner-softmax denominator.
            u64 s01 = add2(add2(e2[bb][0], e2[bb][1]), add2(e2[bb][2], e2[bb][3]));
            u64 s23 = add2(add2(e2[bb][4], e2[bb][5]), add2(e2[bb][6], e2[bb][7]));
            u64 st  = add2(s01, s23);
            float slo, shi; unpack2(st, slo, shi);
            inv[bb] = rcpf(slo + shi);
            // Agreement dot with Vq (f32).
            u64 g = mul2(e2[bb][0], Vq2[0]);
#pragma unroll
            for (int k = 1; k < 8; k++) g = fma2(e2[bb][k], Vq2[k], g);
            float glo, ghi; unpack2(g, glo, ghi);
            const float ag = (glo + ghi) * inv[bb];
            stcs(agree_out + (((size_t)(b0 + bb) * NIN) + n0 + i) * MM + tid, ag);
            eag[bb] = ex2f(ag * LOG2E);   // |ag| <= 1, max-free softmax safe (f32)
        }

        // Pre-barrier: half-warp split reduce. Swap bb roles across halves,
        // then 4 xor levels within each half. Lanes 0-15 -> warp bb0 partial,
        // lanes 16-31 -> warp bb1 partial. 5 SHFL total (was 10).
        {
            const bool hi_half = (lane & 16) != 0;
            const float mine  = hi_half ? eag[1] : eag[0];
            const float yours = hi_half ? eag[0] : eag[1];
            float s = mine + __shfl_xor_sync(0xffffffffu, yours, 16);
            s += __shfl_xor_sync(0xffffffffu, s, 1);
            s += __shfl_xor_sync(0xffffffffu, s, 2);
            s += __shfl_xor_sync(0xffffffffu, s, 4);
            s += __shfl_xor_sync(0xffffffffu, s, 8);
            const int buf = i & 1;
            if (lane == 0)  sred[buf][wid]      = s;   // bb0 partial
            if (lane == 16) sred[buf][16 + wid] = s;   // bb1 partial
        }
        __syncthreads();
        // Post-barrier: every warp redundantly reduces: lanes 0-15 -> bb0,
        // 16-31 -> bb1 (unchanged round-14 shuffle scheme).
        const int buf = i & 1;
        float z = sred[buf][lane];
#pragma unroll
        for (int o = 8; o > 0; o >>= 1) z += __shfl_xor_sync(0xffffffffu, z, o);
        const float S0 = __shfl_sync(0xffffffffu, z, 0);
        const float S1 = __shfl_sync(0xffffffffu, z, 16);

        const float q0 = eag[0] * rcpf(S0) * inv[0];
        const float q1 = eag[1] * rcpf(S1) * inv[1];
        const u64 q0d = pack2(q0, q0);
        const u64 q1d = pack2(q1, q1);
#pragma unroll
        for (int k = 0; k < 8; k++) {
            acc2[0][k] = fma2(q0d, e2[0][k], acc2[0][k]);
            acc2[1][k] = fma2(q1d, e2[1][k], acc2[1][k]);
        }
    }

    // acc2[bb] as u64[8] is already float[16] in natural slot order.
#pragma unroll
    for (int bb = 0; bb < BPG; bb++) {
        float4* dst = (float4*)(g_partial +
            ((((size_t)chunk * BB + (b0 + bb)) * MM + tid) << 4));
#pragma unroll
        for (int q = 0; q < 4; q++) {
            float xx, yy, zz, ww;
            unpack2(acc2[bb][2 * q],     xx, yy);
            unpack2(acc2[bb][2 * q + 1], zz, ww);
            dst[q] = make_float4(xx, yy, zz, ww);
        }
    }
}

// Reduce chunk partials + LayerNorm. 8 lanes cooperate per (b,m) row:
// q = float4 quarter (0..3), h = chunk half (0..1; 9 chunks each).
__global__ __launch_bounds__(256)
void caps_ln(const float* __restrict__ gamma,
             const float* __restrict__ beta,
             float* __restrict__ nv_out)  // [B*MM, 16]
{
    const int t   = blockIdx.x * 256 + threadIdx.x;  // 0 .. B*MM*8-1
    const int row = t >> 3;
    const int q   = t & 3;
    const int h   = (t >> 2) & 1;
    const int b   = row / MM;
    const int m   = row % MM;

    float4 v = make_float4(0.f, 0.f, 0.f, 0.f);
#pragma unroll
    for (int cc = 0; cc < NCHUNK / 2; cc++) {
        const int c = h * (NCHUNK / 2) + cc;
        const float4 p = *(const float4*)(g_partial +
            ((((size_t)c * BB + b) * MM + m) << 4) + q * 4);
        v.x += p.x; v.y += p.y; v.z += p.z; v.w += p.w;
    }
    // Combine chunk halves (lanes differ in bit 2).
    v.x += __shfl_xor_sync(0xffffffffu, v.x, 4);
    v.y += __shfl_xor_sync(0xffffffffu, v.y, 4);
    v.z += __shfl_xor_sync(0xffffffffu, v.z, 4);
    v.w += __shfl_xor_sync(0xffffffffu, v.w, 4);

    // Row stats across the 4 q-lanes (bits 0-1).
    float s = v.x + v.y + v.z + v.w;
    s += __shfl_xor_sync(0xffffffffu, s, 1);
    s += __shfl_xor_sync(0xffffffffu, s, 2);
    const float mu = s * (1.0f / 16.0f);

    const float d0 = v.x - mu, d1 = v.y - mu, d2 = v.z - mu, d3 = v.w - mu;
    float ss = d0 * d0 + d1 * d1 + d2 * d2 + d3 * d3;
    ss += __shfl_xor_sync(0xffffffffu, ss, 1);
    ss += __shfl_xor_sync(0xffffffffu, ss, 2);
    const float rs = rsqrtf(ss * (1.0f / 16.0f) + LN_EPS);

    if (h == 0) {
        const float4 gm = *(const float4*)(gamma + q * 4);
        const float4 bt = *(const float4*)(beta + q * 4);
        float4 o;
        o.x = d0 * rs * gm.x + bt.x;
        o.y = d1 * rs * gm.y + bt.y;
        o.z = d2 * rs * gm.z + bt.z;
        o.w = d3 * rs * gm.w + bt.w;
        *(float4*)(nv_out + (size_t)row * 16 + q * 4) = o;
    }
}

extern "C" void kernel_launch(void* const* d_in, const int* in_sizes, int n_in,
                              void* d_out, int out_size)
{
    // metadata order: input, num_iter, w, V, gamma, beta
    const float* x     = (const float*)d_in[0];
    const float* w     = (const float*)d_in[2];
    const float* V     = (const float*)d_in[3];
    const float* gamma = (const float*)d_in[4];
    const float* beta  = (const float*)d_in[5];

    float* out    = (float*)d_out;
    float* nv_out = out;                          // [16,512,16]   = 131072
    float* agree  = out + (size_t)BB * MM * 16;   // [16,1024,512] = 8388608

    caps_main<<<NCHUNK * (BB / BPG), 512>>>(x, w, V, agree);
    caps_ln<<<(BB * MM * 8) / 256, 256>>>(gamma, beta, nv_out);
}